// round 1
// baseline (speedup 1.0000x reference)
#include <cuda_runtime.h>

// Inclusive cumsum along leading axis of xs[T, D] (row-major), fp32.
// Output layout: d_out[0:D] = final carry (ys[T-1]), d_out[D : D + T*D] = ys.
//
// 3-pass chunked scan:
//   pass1: per-chunk column sums          (reads all data once)
//   pass2: exclusive scan of chunk sums along chunk dim; writes carry
//   pass3: apply chunk prefix, stream rows, write ys
//
// Scratch: __device__ global (no allocations allowed).

#define SCAN_THREADS 256
#define MAX_CHUNKS   128
#define MAX_D        4096

static __device__ float g_partials[MAX_CHUNKS * MAX_D];

// ---------------------------------------------------------------------------
// Pass 1: each CTA covers (1024 columns) x (R rows). One float4 per thread.
// grid = (D/4/SCAN_THREADS, CHUNKS)
__global__ void scan_pass1(const float* __restrict__ xs, int D, int R) {
    const int stride4 = D >> 2;                       // float4s per row
    const int col4 = blockIdx.x * blockDim.x + threadIdx.x;
    const int chunk = blockIdx.y;
    if (col4 >= stride4) return;

    const float4* __restrict__ x =
        reinterpret_cast<const float4*>(xs) + (size_t)chunk * R * stride4 + col4;

    float4 acc = make_float4(0.f, 0.f, 0.f, 0.f);
#pragma unroll 8
    for (int i = 0; i < R; ++i) {
        float4 v = x[(size_t)i * stride4];
        acc.x += v.x; acc.y += v.y; acc.z += v.z; acc.w += v.w;
    }
    reinterpret_cast<float4*>(g_partials)[(size_t)chunk * stride4 + col4] = acc;
}

// ---------------------------------------------------------------------------
// Pass 2: exclusive scan over chunks for each column; the final running sum
// is the column total == final carry, written straight to d_out[0:D].
// grid = (D / SCAN_THREADS)
__global__ void scan_pass2(float* __restrict__ carry_out, int D, int chunks) {
    const int col = blockIdx.x * blockDim.x + threadIdx.x;
    if (col >= D) return;

    float running = 0.f;
    for (int c = 0; c < chunks; ++c) {
        float s = g_partials[(size_t)c * D + col];
        g_partials[(size_t)c * D + col] = running;   // exclusive prefix
        running += s;
    }
    carry_out[col] = running;                         // final carry
}

// ---------------------------------------------------------------------------
// Pass 3: seed with exclusive chunk prefix, stream rows, write ys.
// grid = (D/4/SCAN_THREADS, CHUNKS)
__global__ void scan_pass3(const float* __restrict__ xs,
                           float* __restrict__ ys, int D, int R) {
    const int stride4 = D >> 2;
    const int col4 = blockIdx.x * blockDim.x + threadIdx.x;
    const int chunk = blockIdx.y;
    if (col4 >= stride4) return;

    const float4* __restrict__ x =
        reinterpret_cast<const float4*>(xs) + (size_t)chunk * R * stride4 + col4;
    float4* __restrict__ y =
        reinterpret_cast<float4*>(ys) + (size_t)chunk * R * stride4 + col4;

    float4 acc = reinterpret_cast<const float4*>(g_partials)[(size_t)chunk * stride4 + col4];

#pragma unroll 8
    for (int i = 0; i < R; ++i) {
        float4 v = x[(size_t)i * stride4];
        acc.x += v.x; acc.y += v.y; acc.z += v.z; acc.w += v.w;
        y[(size_t)i * stride4] = acc;
    }
}

// ---------------------------------------------------------------------------
extern "C" void kernel_launch(void* const* d_in, const int* in_sizes, int n_in,
                              void* d_out, int out_size) {
    const float* xs = (const float*)d_in[0];
    float* out = (float*)d_out;

    const int total = in_sizes[0];          // T * D
    int D = out_size - total;               // tuple: carry[D] + ys[T*D]
    if (D <= 0 || total % D != 0) D = 4096; // safety for expected shape
    const int T = total / D;

    // Pick chunk count: as many as possible (<= MAX_CHUNKS) dividing T.
    int chunks = MAX_CHUNKS;
    while (chunks > 1 && (T % chunks) != 0) chunks >>= 1;
    const int R = T / chunks;

    float* carry = out;        // [D]
    float* ys    = out + D;    // [T, D]

    const int stride4 = D / 4;
    dim3 grid1((stride4 + SCAN_THREADS - 1) / SCAN_THREADS, chunks);

    scan_pass1<<<grid1, SCAN_THREADS>>>(xs, D, R);
    scan_pass2<<<(D + SCAN_THREADS - 1) / SCAN_THREADS, SCAN_THREADS>>>(carry, D, chunks);
    scan_pass3<<<grid1, SCAN_THREADS>>>(xs, ys, D, R);
}

// round 2
// speedup vs baseline: 1.1269x; 1.1269x over previous
#include <cuda_runtime.h>

// Single-pass inclusive cumsum along leading axis of xs[T, D] (fp32, row-major)
// using decoupled lookback. Output: d_out[0:D] = final carry, d_out[D:] = ys.
//
// Tile = 32 rows x 1024 cols, staged in smem (xs read exactly once from DRAM).
// Per-column-lane status flags with acquire/release for the lookback protocol.

#define THREADS   512
#define C_F4      256          // float4 columns per group (1024 floats)
#define ROWS      32
#define HALF      16           // rows per thread (two halves of 256 threads)
#define MAX_CHUNKS 256
#define MAX_SP4    1024        // max padded stride in float4

static __device__ float4 g_agg4[MAX_CHUNKS * MAX_SP4];  // tile aggregates
static __device__ float4 g_inc4[MAX_CHUNKS * MAX_SP4];  // inclusive prefixes
static __device__ int    g_stat[MAX_CHUNKS * MAX_SP4];  // 0=none 1=agg 2=inclusive

__device__ __forceinline__ int ld_acquire(const int* p) {
    int v;
    asm volatile("ld.acquire.gpu.global.b32 %0, [%1];" : "=r"(v) : "l"(p) : "memory");
    return v;
}
__device__ __forceinline__ void st_release(int* p, int v) {
    asm volatile("st.release.gpu.global.b32 [%0], %1;" :: "l"(p), "r"(v) : "memory");
}
__device__ __forceinline__ float4 f4add(float4 a, float4 b) {
    return make_float4(a.x + b.x, a.y + b.y, a.z + b.z, a.w + b.w);
}

__global__ __launch_bounds__(THREADS, 1)
void scan_lookback(const float4* __restrict__ xs4, float4* __restrict__ ys4,
                   float4* __restrict__ carry4,
                   int stride4, int sp4, int T, int chunks) {
    extern __shared__ float4 sm[];
    float4* tile = sm;                    // [ROWS][C_F4] running prefixes
    float4* auxh = sm + ROWS * C_F4;      // [2][C_F4] per-half totals
    float4* auxe = auxh + 2 * C_F4;       // [C_F4] exclusive chunk prefix

    const int g   = blockIdx.x;           // column group
    const int c   = blockIdx.y;           // chunk along T (bid chunk-major)
    const int tid = threadIdx.x;
    const int t4  = tid & (C_F4 - 1);
    const int h   = tid >> 8;             // 0 or 1
    const int gc4 = g * C_F4 + t4;        // global float4 column
    const bool act = gc4 < stride4;

    const int row0 = c * ROWS + h * HALF;
    const float4* xp = xs4 + (size_t)row0 * stride4 + gc4;

    // ---- Phase A: stream rows once, build running prefix in smem ----
    float4 acc = make_float4(0.f, 0.f, 0.f, 0.f);
#pragma unroll
    for (int r = 0; r < HALF; ++r) {
        float4 v = make_float4(0.f, 0.f, 0.f, 0.f);
        if (act && (row0 + r) < T) v = __ldcs(xp + (size_t)r * stride4);
        acc = f4add(acc, v);
        tile[(h * HALF + r) * C_F4 + t4] = acc;
    }
    auxh[h * C_F4 + t4] = acc;
    __syncthreads();

    // ---- Publish aggregate + lookback (half-0 threads, one per column) ----
    float4 agg = make_float4(0.f, 0.f, 0.f, 0.f);
    float4 ex  = make_float4(0.f, 0.f, 0.f, 0.f);
    if (h == 0) {
        agg = f4add(auxh[t4], auxh[C_F4 + t4]);
        const size_t lane = (size_t)c * sp4 + gc4;
        if (act) {
            g_agg4[lane] = agg;
            if (c == 0) {
                g_inc4[lane] = agg;
                st_release(&g_stat[lane], 2);
            } else {
                st_release(&g_stat[lane], 1);
            }
        }
        if (c > 0 && act) {
            int p = c - 1;
            for (;;) {
                const size_t pl = (size_t)p * sp4 + gc4;
                int s;
                do { s = ld_acquire(&g_stat[pl]); } while (s == 0);
                ex = f4add(ex, (s == 2) ? g_inc4[pl] : g_agg4[pl]);
                if (s == 2) break;
                --p;
            }
            g_inc4[lane] = f4add(ex, agg);
            st_release(&g_stat[lane], 2);
        }
        auxe[t4] = ex;
        if (c == chunks - 1 && act)
            carry4[gc4] = f4add(ex, agg);   // final carry
    }
    __syncthreads();

    // ---- Phase B: add prefix, stream ys out ----
    float4 base = auxe[t4];
    if (h == 1) base = f4add(base, auxh[t4]);   // add half-0 total

    float4* yp = ys4 + (size_t)row0 * stride4 + gc4;
#pragma unroll
    for (int r = 0; r < HALF; ++r) {
        if (act && (row0 + r) < T) {
            float4 v = f4add(tile[(h * HALF + r) * C_F4 + t4], base);
            __stcs(yp + (size_t)r * stride4, v);
        }
    }
}

// ---------------------------------------------------------------------------
extern "C" void kernel_launch(void* const* d_in, const int* in_sizes, int n_in,
                              void* d_out, int out_size) {
    const float* xs = (const float*)d_in[0];
    float* out = (float*)d_out;

    const int total = in_sizes[0];          // T * D
    int D = out_size - total;               // tuple: carry[D] + ys[T*D]
    if (D <= 0 || total % D != 0) D = 4096;
    const int T = total / D;

    const int stride4 = D / 4;
    const int ngroups = (stride4 + C_F4 - 1) / C_F4;
    const int sp4     = ngroups * C_F4;     // padded stride for scratch
    const int chunks  = (T + ROWS - 1) / ROWS;

    float* carry = out;        // [D]
    float* ys    = out + D;    // [T, D]

    // Reset status flags (graph-capturable memset node).
    void* stat_ptr = nullptr;
    cudaGetSymbolAddress(&stat_ptr, g_stat);
    cudaMemsetAsync(stat_ptr, 0, (size_t)chunks * sp4 * sizeof(int));

    const int smem_bytes = (ROWS * C_F4 + 3 * C_F4) * (int)sizeof(float4);
    cudaFuncSetAttribute(scan_lookback,
                         cudaFuncAttributeMaxDynamicSharedMemorySize, smem_bytes);

    dim3 grid(ngroups, chunks);
    scan_lookback<<<grid, THREADS, smem_bytes>>>(
        (const float4*)xs, (float4*)ys, (float4*)carry,
        stride4, sp4, T, chunks);
}